// round 1
// baseline (speedup 1.0000x reference)
#include <cuda_runtime.h>

#define N_ENTITY 500000
#define N_REL    32
#define DIM      64
#define NHOP     2
#define N_ITEM   10000
#define N_MEM    32
#define BATCH    4096
#define HIST     50

// Scratch: per-item accumulated embedding after both attention hops.
// 10000 * 64 * 4B = 2.56 MB (static __device__, allocation-free).
__device__ float g_acc[N_ITEM * DIM];

__device__ __forceinline__ float warp_sum(float v) {
    #pragma unroll
    for (int off = 16; off > 0; off >>= 1)
        v += __shfl_xor_sync(0xffffffffu, v, off);
    return v;
}

// ---------------------------------------------------------------------------
// Kernel 1: per-item attention over 2 hops x 32 memories.
// One block (256 thr = 8 warps) per item. Warp w owns memories {w, w+8, w+16, w+24}.
// Lane l holds embedding dims [2l, 2l+1] as float2 -> each row gather is one
// coalesced LDG.64 covering the full 256B row across the warp.
// ---------------------------------------------------------------------------
__global__ __launch_bounds__(256, 8)
void item_acc_kernel(const float* __restrict__ entity_emb,
                     const float* __restrict__ relation_emb,
                     const float* __restrict__ W_w,
                     const float* __restrict__ W_b,
                     const int*   __restrict__ item_ids,
                     const int*   __restrict__ heads,
                     const int*   __restrict__ relations,
                     const int*   __restrict__ tails)
{
    const int item = blockIdx.x;
    const int tid  = threadIdx.x;
    const int wid  = tid >> 5;    // 0..7
    const int lane = tid & 31;

    __shared__ float acc_s[DIM];
    __shared__ float e_s[N_MEM];
    __shared__ float denom_s;

    // Per-lane float2 slices of the projection weights (dims 2l, 2l+1).
    const float2 wh = reinterpret_cast<const float2*>(W_w)[lane];
    const float2 wr = reinterpret_cast<const float2*>(W_w + DIM)[lane];
    const float2 wt = reinterpret_cast<const float2*>(W_w + 2 * DIM)[lane];
    const float  bias = W_b[0];

    if (tid < DIM)
        acc_s[tid] = entity_emb[(long long)item_ids[item] * DIM + tid];
    __syncthreads();

    const float2* ee = reinterpret_cast<const float2*>(entity_emb);
    const float2* re = reinterpret_cast<const float2*>(relation_emb);

    for (int h = 0; h < NHOP; ++h) {
        const int base = (h * N_ITEM + item) * N_MEM;

        float2 te[4];
        float  eexp[4];

        #pragma unroll
        for (int k = 0; k < 4; ++k) {
            const int m  = wid + 8 * k;
            const int hi = heads[base + m];
            const int ri = relations[base + m];
            const int ti = tails[base + m];

            const float2 he = ee[hi * (DIM / 2) + lane];
            const float2 rv = re[ri * (DIM / 2) + lane];
            const float2 tv = ee[ti * (DIM / 2) + lane];
            te[k] = tv;

            float p = wh.x * he.x + wh.y * he.y
                    + wr.x * rv.x + wr.y * rv.y
                    + wt.x * tv.x + wt.y * tv.y;
            p = warp_sum(p);
            const float logit = p + bias;
            const float s = 1.0f / (1.0f + expf(-logit));
            eexp[k] = expf(s);   // softmax numerator; s in (0,1) so no max-sub needed
        }

        if (lane == 0) {
            #pragma unroll
            for (int k = 0; k < 4; ++k)
                e_s[wid + 8 * k] = eexp[k];
        }
        __syncthreads();

        if (wid == 0) {
            float v = e_s[lane];
            v = warp_sum(v);
            if (lane == 0) denom_s = v;
        }
        __syncthreads();

        const float inv = 1.0f / denom_s;
        float2 pacc = make_float2(0.0f, 0.0f);
        #pragma unroll
        for (int k = 0; k < 4; ++k) {
            const float pi = eexp[k] * inv;
            pacc.x += pi * te[k].x;
            pacc.y += pi * te[k].y;
        }
        atomicAdd(&acc_s[2 * lane + 0], pacc.x);
        atomicAdd(&acc_s[2 * lane + 1], pacc.y);
        __syncthreads();   // acc_s complete; e_s/denom_s safe to reuse next hop
    }

    if (tid < DIM)
        g_acc[item * DIM + tid] = acc_s[tid];
}

// ---------------------------------------------------------------------------
// Kernel 2: user pooling + scoring. One warp per batch row.
// ---------------------------------------------------------------------------
__global__ __launch_bounds__(256)
void user_score_kernel(const float* __restrict__ entity_emb,
                       const int*   __restrict__ records_idx,
                       const int*   __restrict__ items,
                       float*       __restrict__ out)
{
    const int warp = (blockIdx.x * blockDim.x + threadIdx.x) >> 5;
    const int lane = threadIdx.x & 31;
    if (warp >= BATCH) return;

    const int* rec = records_idx + warp * HIST;
    const float2* acc2 = reinterpret_cast<const float2*>(g_acc);

    float2 u = make_float2(0.0f, 0.0f);
    #pragma unroll 5
    for (int j = 0; j < HIST; ++j) {
        const int idx = rec[j];                    // uniform across warp
        const float2 a = acc2[idx * (DIM / 2) + lane];
        u.x += a.x;
        u.y += a.y;
    }

    const int it = items[warp];
    const float2 p = reinterpret_cast<const float2*>(entity_emb)[it * (DIM / 2) + lane];
    float dot = u.x * p.x + u.y * p.y;
    dot = warp_sum(dot);

    if (lane == 0)
        out[warp] = 1.0f / (1.0f + expf(-dot));
}

// ---------------------------------------------------------------------------
// Launch
// ---------------------------------------------------------------------------
extern "C" void kernel_launch(void* const* d_in, const int* in_sizes, int n_in,
                              void* d_out, int out_size)
{
    const float* entity_emb   = (const float*)d_in[0];
    const float* relation_emb = (const float*)d_in[1];
    const float* W_w          = (const float*)d_in[2];
    const float* W_b          = (const float*)d_in[3];
    const int*   item_ids     = (const int*)d_in[4];
    const int*   heads        = (const int*)d_in[5];
    const int*   relations    = (const int*)d_in[6];
    const int*   tails        = (const int*)d_in[7];
    const int*   records_idx  = (const int*)d_in[8];
    const int*   items        = (const int*)d_in[9];
    float*       out          = (float*)d_out;

    item_acc_kernel<<<N_ITEM, 256>>>(entity_emb, relation_emb, W_w, W_b,
                                     item_ids, heads, relations, tails);

    const int warps_per_block = 256 / 32;
    const int blocks = (BATCH + warps_per_block - 1) / warps_per_block;
    user_score_kernel<<<blocks, 256>>>(entity_emb, records_idx, items, out);
}